// round 12
// baseline (speedup 1.0000x reference)
#include <cuda_runtime.h>

// SpatialTransformer: out = trilinear_sample(src, identity_grid + flow), border clamp.
// src:  [1,1,160,192,160] f32   d_in[0]
// flow: [1,3,160,192,160] f32   d_in[1]  (channel-planar: d,h,w displacement)
// grid: identity meshgrid       d_in[2]  (IGNORED - recomputed from indices)
// out:  [1,1,160,192,160] f32
//
// Math collapse (verified, rel_err 2.6e-5):
//   ux = (w + flow[2]) * W/(W-1) - 0.5 ; clamp [0, W-1]; trilinear w/ clamped +1.
//
// R11 confirmed: 3D tiling (32x x 8h x 4z per block) makes gathers L1-resident
// (L2% 68->43). Binding resource now = L1 wavefront throughput, ~6 wf/voxel
// (4 aligned float2 + 4 fix-ups @50% active). R12: shifted shadow B[i]=src[i+1]
// so every x-pair is ONE aligned float2 (even x0 -> src, odd x0 -> B at x0-1):
// 4 wf/voxel, no fix-ups, no selects. Footprint ~72KB still << L1.

#define DD 160
#define HH 192
#define WW 160
#define PLANE (HH * WW)
#define NN (DD * HH * WW)
#define ZB 4   // z-batch per thread

// shifted shadow of src (+ tail pad, zero-filled by the copy kernel)
__device__ __align__(16) float g_srcB[NN + 4];

__global__ __launch_bounds__(256) void shift_copy_kernel(const float* __restrict__ src)
{
    const int i4 = blockIdx.x * blockDim.x + threadIdx.x;
    if (i4 >= (NN + 4) / 4) return;
    const int j = i4 * 4;

    float4 v;
    v.x = (j + 1 < NN) ? __ldg(src + j + 1) : 0.0f;
    v.y = (j + 2 < NN) ? __ldg(src + j + 2) : 0.0f;
    v.z = (j + 3 < NN) ? __ldg(src + j + 3) : 0.0f;
    v.w = (j + 4 < NN) ? __ldg(src + j + 4) : 0.0f;
    *(float4*)(g_srcB + j) = v;
}

__global__ void st_warp_tile_sh_kernel(
    const float* __restrict__ src,
    const float* __restrict__ flow,
    float* __restrict__ out)
{
    // 3D tile: 32 (x) x 8 (h) x ZB (z) voxels per block, 256 threads
    const int w  = blockIdx.x * 32 + threadIdx.x;
    const int h  = blockIdx.y * 8 + threadIdx.y;
    const int d0 = blockIdx.z * ZB;
    const int base = (d0 * HH + h) * WW + w;

    const float sx = (float)WW / (float)(WW - 1);
    const float sy = (float)HH / (float)(HH - 1);
    const float sz = (float)DD / (float)(DD - 1);

    // front-batched flow loads (one latency exposure; warp-coalesced: tx fastest)
    float fdv[ZB], fhv[ZB], fwv[ZB];
#pragma unroll
    for (int k = 0; k < ZB; k++) {
        const int idx = base + k * PLANE;
        fdv[k] = __ldg(flow + idx);            // D-displacement
        fhv[k] = __ldg(flow + NN + idx);       // H-displacement
        fwv[k] = __ldg(flow + 2 * NN + idx);   // W-displacement
    }

    float res[ZB];
#pragma unroll
    for (int k = 0; k < ZB; k++) {
        const int d = d0 + k;

        float ux = ((float)w + fwv[k]) * sx - 0.5f;
        float uy = ((float)h + fhv[k]) * sy - 0.5f;
        float uz = ((float)d + fdv[k]) * sz - 0.5f;

        ux = fminf(fmaxf(ux, 0.0f), (float)(WW - 1));
        uy = fminf(fmaxf(uy, 0.0f), (float)(HH - 1));
        uz = fminf(fmaxf(uz, 0.0f), (float)(DD - 1));

        // coords >= 0 -> truncation == floor
        const int x0 = (int)ux;
        const int y0 = (int)uy;
        const int z0 = (int)uz;
        const float ax = ux - (float)x0;
        const float ay = uy - (float)y0;
        const float az = uz - (float)z0;

        const int y1 = min(y0 + 1, HH - 1);
        const int z1 = min(z0 + 1, DD - 1);

        // one aligned float2 covers (x0, x0+1): src for even x0, shadow B for
        // odd x0 (B[x0-1]=src[x0], B[x0]=src[x0+1]). When x0 == WW-1 the hi
        // element is next-row garbage multiplied by exactly ax == 0.
        const bool odd = (x0 & 1) != 0;
        const float* pb = odd ? (g_srcB + (x0 - 1)) : (src + x0);

        const int zy00 = (z0 * HH + y0) * WW;
        const int zy01 = (z0 * HH + y1) * WW;
        const int zy10 = (z1 * HH + y0) * WW;
        const int zy11 = (z1 * HH + y1) * WW;

        const float2 v00 = __ldg((const float2*)(pb + zy00));
        const float2 v01 = __ldg((const float2*)(pb + zy01));
        const float2 v10 = __ldg((const float2*)(pb + zy10));
        const float2 v11 = __ldg((const float2*)(pb + zy11));

        const float c00 = fmaf(ax, v00.y - v00.x, v00.x);
        const float c01 = fmaf(ax, v01.y - v01.x, v01.x);
        const float c10 = fmaf(ax, v10.y - v10.x, v10.x);
        const float c11 = fmaf(ax, v11.y - v11.x, v11.x);

        const float c0 = fmaf(ay, c01 - c00, c00);
        const float c1 = fmaf(ay, c11 - c10, c10);
        res[k] = fmaf(az, c1 - c0, c0);
    }

#pragma unroll
    for (int k = 0; k < ZB; k++)
        out[base + k * PLANE] = res[k];
}

extern "C" void kernel_launch(void* const* d_in, const int* in_sizes, int n_in,
                              void* d_out, int out_size)
{
    const float* src  = (const float*)d_in[0];
    const float* flow = (const float*)d_in[1];
    // d_in[2] (identity grid) intentionally unused — recomputed from indices.
    float* out = (float*)d_out;

    // 1) build shifted shadow copy (deterministic, graph-capturable)
    const int threads = 256;
    const int copy_blocks = ((NN + 4) / 4 + threads - 1) / threads;
    shift_copy_kernel<<<copy_blocks, threads>>>(src);

    // 2) tiled warp kernel (same stream -> ordered after the copy)
    dim3 block(32, 8, 1);
    dim3 grid(WW / 32, HH / 8, DD / ZB);   // 5 x 24 x 40 = 4800 blocks
    st_warp_tile_sh_kernel<<<grid, block>>>(src, flow, out);
}